// round 6
// baseline (speedup 1.0000x reference)
#include <cuda_runtime.h>
#include <cuda_fp16.h>

#define IH 256
#define IW 256
#define NPIX (IH * IW)          // 65536
#define NMAPS 88
#define SRC_ELEMS (NPIX * 3)    // 196608

#define QSTRIDE 132
#define QROWS 129
#define COPYSZ (QROWS * QSTRIDE)    // 17028

#define BP 258                      // padded b-plane dim
#define BPL_ELEMS (BP * BP)         // 66564 (even)
#define SMEM_BYTES (BPL_ELEMS * 2)  // 133128

#define NUNITS (NMAPS * NPIX / 2)   // 2,883,584 units (2 px each)
#define PGRID 148
#define PBLOCK 1024

// rg-quad: 2x2 corners, each corner = half2(r,g) -> uint. Layout [nw,ne,sw,se] = 16B.
// Copy (py,px): quad (ky,kx) covers rows (2ky-py, 2ky-py+1), cols (2kx-px, 2kx-px+1).
// OOB corners stored as zero (bakes the reference's corner masks).
__device__ uint4 g_rgq[4 * COPYSZ];            // ~1.09 MB, L2-resident
__device__ unsigned short g_bpl[BPL_ELEMS];    // padded fp16 b-plane (zero border)

__device__ __forceinline__ unsigned rg_fetch(const float* __restrict__ s, int r, int c) {
    if ((unsigned)r < IH && (unsigned)c < IW) {
        const float* p = s + (r * IW + c) * 3;
        __half2 h = __halves2half2(__float2half(p[0]), __float2half(p[1]));
        return *reinterpret_cast<unsigned*>(&h);
    }
    return 0u;
}

__global__ void pack_src_kernel(const float* __restrict__ src) {
    int t = blockIdx.x * blockDim.x + threadIdx.x;
    if (t < BPL_ELEMS) {     // padded b-plane, zero border
        int r = t / BP - 1;
        int c = t % BP - 1;
        __half h = ((unsigned)r < IH && (unsigned)c < IW)
                     ? __float2half(src[(r * IW + c) * 3 + 2]) : __float2half(0.f);
        g_bpl[t] = *reinterpret_cast<unsigned short*>(&h);
    }
    if (t < 4 * COPYSZ) {    // rg parity quads
        int cc  = t / COPYSZ;
        int rem = t % COPYSZ;
        int ky = rem / QSTRIDE;
        int kx = rem % QSTRIDE;
        int py = cc >> 1, px = cc & 1;
        int r0 = 2 * ky - py;
        int c0 = 2 * kx - px;
        uint4 q;
        q.x = rg_fetch(src, r0,     c0);
        q.y = rg_fetch(src, r0,     c0 + 1);
        q.z = rg_fetch(src, r0 + 1, c0);
        q.w = rg_fetch(src, r0 + 1, c0 + 1);
        g_rgq[t] = q;
    }
}

__device__ __forceinline__ float2 u2f(unsigned v) {
    __half2 h = *reinterpret_cast<__half2*>(&v);
    return __half22float2(h);
}

__global__ void __launch_bounds__(PBLOCK, 1) deform_kernel(
    const float* __restrict__ motions, float* __restrict__ out) {
    extern __shared__ char smem[];
    __half* sb = reinterpret_cast<__half*>(smem);

    // fill b-plane into smem, coalesced 32-bit copies
    {
        const unsigned* gw = reinterpret_cast<const unsigned*>(g_bpl);
        unsigned* sw = reinterpret_cast<unsigned*>(smem);
        for (int i = threadIdx.x; i < BPL_ELEMS / 2; i += PBLOCK)
            sw[i] = gw[i];
    }
    __syncthreads();

    const float4* m4 = reinterpret_cast<const float4*>(motions);
    float2* o2base = reinterpret_cast<float2*>(out);
    const int stride = PGRID * PBLOCK;
    int gid = blockIdx.x * PBLOCK + threadIdx.x;

    for (int u0 = gid; u0 < NUNITS; u0 += 2 * stride) {
        int u1 = u0 + stride;
        bool has1 = (u1 < NUNITS);

        float4 m0 = __ldcs(&m4[u0]);
        float4 m1 = has1 ? __ldcs(&m4[u1]) : make_float4(0.f, 0.f, 0.f, 0.f);

        float gx[4] = {m0.x, m0.z, m1.x, m1.z};
        float gy[4] = {m0.y, m0.w, m1.y, m1.w};

        float fx[4], fy[4];
        uint4 q[4];
        int bb[4];
#pragma unroll
        for (int s = 0; s < 4; s++) {
            float x = fmaf(gx[s], 128.f, 127.5f);   // [-0.5, 255.5)
            float y = fmaf(gy[s], 128.f, 127.5f);
            int xw = __float2int_rd(x);   // [-1, 255]
            int yn = __float2int_rd(y);   // [-1, 255]
            fx[s] = x - (float)xw;
            fy[s] = y - (float)yn;
            int py = yn & 1, px = xw & 1;
            int ky = (yn + py) >> 1;      // [0,128]
            int kx = (xw + px) >> 1;      // [0,128]
            q[s] = __ldg(&g_rgq[((py << 1) | px) * COPYSZ + ky * QSTRIDE + kx]);
            bb[s] = (yn + 1) * BP + (xw + 1);
        }

        // b-channel from smem (4 LDS.16 per sample), zero border bakes masks
        float bnw[4], bne[4], bsw[4], bse[4];
#pragma unroll
        for (int s = 0; s < 4; s++) {
            bnw[s] = __half2float(sb[bb[s]]);
            bne[s] = __half2float(sb[bb[s] + 1]);
            bsw[s] = __half2float(sb[bb[s] + BP]);
            bse[s] = __half2float(sb[bb[s] + BP + 1]);
        }

        float r[12];
#pragma unroll
        for (int s = 0; s < 4; s++) {
            float wnw = (1.f - fy[s]) * (1.f - fx[s]);
            float wne = (1.f - fy[s]) * fx[s];
            float wsw = fy[s] * (1.f - fx[s]);
            float wse = fy[s] * fx[s];
            float2 nw = u2f(q[s].x), ne = u2f(q[s].y);
            float2 sw = u2f(q[s].z), se = u2f(q[s].w);
            r[s * 3 + 0] = wnw * nw.x + wne * ne.x + wsw * sw.x + wse * se.x;
            r[s * 3 + 1] = wnw * nw.y + wne * ne.y + wsw * sw.y + wse * se.y;
            r[s * 3 + 2] = wnw * bnw[s] + wne * bne[s] + wsw * bsw[s] + wse * bse[s];
        }

        float2* o0 = o2base + (size_t)u0 * 3;
        __stcs(&o0[0], make_float2(r[0], r[1]));
        __stcs(&o0[1], make_float2(r[2], r[3]));
        __stcs(&o0[2], make_float2(r[4], r[5]));
        if (has1) {
            float2* o1 = o2base + (size_t)u1 * 3;
            __stcs(&o1[0], make_float2(r[6],  r[7]));
            __stcs(&o1[1], make_float2(r[8],  r[9]));
            __stcs(&o1[2], make_float2(r[10], r[11]));
        }
    }
}

extern "C" void kernel_launch(void* const* d_in, const int* in_sizes, int n_in,
                              void* d_out, int out_size) {
    const float* source  = (const float*)d_in[0];
    const float* motions = (const float*)d_in[1];
    if (n_in >= 2 && in_sizes[0] != SRC_ELEMS) {
        source  = (const float*)d_in[1];
        motions = (const float*)d_in[0];
    }

    cudaFuncSetAttribute(deform_kernel,
                         cudaFuncAttributeMaxDynamicSharedMemorySize, SMEM_BYTES);

    int pack_threads = 4 * COPYSZ;   // 68112 >= BPL_ELEMS
    pack_src_kernel<<<(pack_threads + 255) / 256, 256>>>(source);
    deform_kernel<<<PGRID, PBLOCK, SMEM_BYTES>>>(motions, (float*)d_out);
}